// round 4
// baseline (speedup 1.0000x reference)
#include <cuda_runtime.h>
#include <cstdint>

// YOLO loss, single kernel, cp.async double-buffered pipeline.
// pred [8192, 49*30] f32, target [8192, 49*25] f32 -> scalar f32.
// 784 blocks x 128 threads, 4 tiles of 128 cells per block.
// Tile t+1's global->shared copy (cp.async) overlaps tile t's compute.

#define YS2       49
#define YB_P      30            // floats per cell (pred)
#define YB_T      25            // floats per cell (target)
#define CELLS     128           // cells per tile (= threads)
#define TILES     4             // tiles per block
#define NBLOCKS   784           // 401408 / (128*4)
#define NBATCH    8192.0

#define TILE_PF   (CELLS * YB_P)        // 3840 floats
#define TILE_TF   (CELLS * YB_T)        // 3200 floats
#define STAGE_F   (TILE_PF + TILE_TF)   // 7040 floats per stage
#define SMEM_BYTES (2 * STAGE_F * 4)    // 56320 B

__device__ double       g_partials[NBLOCKS];
__device__ unsigned int g_ticket;       // zero-init; reset by last block

__device__ __forceinline__ void cp16(uint32_t smem_addr, const void* gptr) {
    asm volatile("cp.async.cg.shared.global [%0], [%1], 16;\n"
                 :: "r"(smem_addr), "l"(gptr));
}

extern __shared__ float dsm[];

__global__ __launch_bounds__(CELLS) void yolo_loss_kernel(
    const float* __restrict__ pred, const float* __restrict__ tgt,
    float* __restrict__ out)
{
    __shared__ float wsum[CELLS / 32];
    __shared__ int   s_last;

    const int b   = blockIdx.x;
    const int tid = threadIdx.x;

    const uint32_t smem_base = (uint32_t)__cvta_generic_to_shared(dsm);

    // ---- issue one tile's cp.async into stage buf ----
    auto issue_tile = [&](int tile, int buf) {
        const float4* gp = (const float4*)pred + (size_t)tile * (TILE_PF / 4);
        const float4* gt = (const float4*)tgt  + (size_t)tile * (TILE_TF / 4);
        const uint32_t sp_a = smem_base + (uint32_t)(buf * STAGE_F) * 4u;
        const uint32_t st_a = sp_a + TILE_PF * 4u;
        #pragma unroll
        for (int k = 0; k < 7; k++)                       // 7*128 = 896 of 960
            cp16(sp_a + (uint32_t)(tid + k * CELLS) * 16u, gp + tid + k * CELLS);
        if (tid < 64)                                     // 960 - 896
            cp16(sp_a + (uint32_t)(tid + 896) * 16u, gp + tid + 896);
        #pragma unroll
        for (int k = 0; k < 6; k++)                       // 6*128 = 768 of 800
            cp16(st_a + (uint32_t)(tid + k * CELLS) * 16u, gt + tid + k * CELLS);
        if (tid < 32)                                     // 800 - 768
            cp16(st_a + (uint32_t)(tid + 768) * 16u, gt + tid + 768);
        asm volatile("cp.async.commit_group;\n");
    };

    issue_tile(b * TILES, 0);

    float acc = 0.0f;

    for (int t = 0; t < TILES; t++) {
        const int tile = b * TILES + t;
        const int buf  = t & 1;

        if (t + 1 < TILES) {
            issue_tile(tile + 1, buf ^ 1);
            asm volatile("cp.async.wait_group 1;\n");
        } else {
            asm volatile("cp.async.wait_group 0;\n");
        }
        __syncthreads();    // tile t's data visible to all threads

        // ---- per-cell loss (reads stage buf) ----
        const float* pc = dsm + buf * STAGE_F + tid * YB_P;
        const float* tc = dsm + buf * STAGE_F + TILE_PF + tid * YB_T;

        const int cell = tile * CELLS + tid;
        const int g    = cell % YS2;
        const float gy = (float)(g / 7);
        const float gx = (float)(g % 7);

        const float t0    = tc[0];
        const float objf  = (t0 == 1.0f) ? 1.0f : 0.0f;
        const float noobf = (t0 == 0.0f) ? 1.0f : 0.0f;

        const float tx = tc[1], ty = tc[2], tw = tc[3], th = tc[4];
        const float tcx = (gx + tx) / 7.0f;
        const float tcy = (gy + ty) / 7.0f;
        const float tx1 = tcx - tw * 0.5f, ty1 = tcy - th * 0.5f;
        const float tx2 = tcx + tw * 0.5f, ty2 = tcy + th * 0.5f;
        const float area_t = (tx2 - tx1) * (ty2 - ty1);

        float iou0, iou1;
        #pragma unroll
        for (int bb = 0; bb < 2; bb++) {
            const float px = fabsf(pc[bb * 5 + 1]);
            const float py = fabsf(pc[bb * 5 + 2]);
            const float pw = fabsf(pc[bb * 5 + 3]);
            const float ph = fabsf(pc[bb * 5 + 4]);
            const float cx = (gx + px) / 7.0f;
            const float cy = (gy + py) / 7.0f;
            const float x1 = cx - pw * 0.5f, y1 = cy - ph * 0.5f;
            const float x2 = cx + pw * 0.5f, y2 = cy + ph * 0.5f;
            const float ltx = fmaxf(x1, tx1), lty = fmaxf(y1, ty1);
            const float rbx = fminf(x2, tx2), rby = fminf(y2, ty2);
            const float iw  = fmaxf(rbx - ltx, 0.0f);
            const float ih  = fmaxf(rby - lty, 0.0f);
            const float inter  = iw * ih;
            const float area_p = (x2 - x1) * (y2 - y1);
            const float v = inter / (area_p + area_t - inter);
            if (bb == 0) iou0 = v; else iou1 = v;
        }

        const int   best    = (iou1 > iou0) ? 1 : 0;
        const float max_iou = best ? iou1 : iou0;
        const float* rbp = pc + best * 5;

        const float dx = rbp[1] - tx;
        const float dy = rbp[2] - ty;
        const float xy_loss = dx * dx + dy * dy;

        const float swd = sqrtf(fabsf(rbp[3])) - sqrtf(fabsf(tw));
        const float shd = sqrtf(fabsf(rbp[4])) - sqrtf(fabsf(th));
        const float wh_loss = swd * swd + shd * shd;

        const float doc = rbp[0] - max_iou;
        const float obj_conf = doc * doc;

        const float noobj_conf = 0.5f * (pc[0] * pc[0] + pc[5] * pc[5]);

        float cls = 0.0f;
        #pragma unroll
        for (int k = 0; k < 20; k++) {
            const float d = pc[10 + k] - tc[5 + k];
            cls += d * d;
        }

        acc += objf * (5.0f * (xy_loss + wh_loss) + obj_conf + cls)
             + noobf * noobj_conf;

        __syncthreads();    // all threads done with buf before it's refilled
    }

    // ---- deterministic block reduction ----
    #pragma unroll
    for (int o = 16; o > 0; o >>= 1)
        acc += __shfl_down_sync(0xffffffffu, acc, o);

    const int lane = tid & 31;
    const int wrp  = tid >> 5;
    if (lane == 0) wsum[wrp] = acc;
    __syncthreads();

    if (tid == 0) {
        double s = 0.0;
        #pragma unroll
        for (int w = 0; w < CELLS / 32; w++) s += (double)wsum[w];
        g_partials[b] = s;
        __threadfence();
        unsigned int ticket = atomicAdd(&g_ticket, 1u);
        s_last = (ticket == NBLOCKS - 1u) ? 1 : 0;
    }
    __syncthreads();

    // ---- last block: final reduction over all partials ----
    if (s_last) {
        __threadfence();
        __shared__ double dsum[CELLS / 32];

        double s = 0.0;
        for (int i = tid; i < NBLOCKS; i += CELLS)
            s += g_partials[i];

        #pragma unroll
        for (int o = 16; o > 0; o >>= 1)
            s += __shfl_down_sync(0xffffffffu, s, o);

        if (lane == 0) dsum[wrp] = s;
        __syncthreads();

        if (tid == 0) {
            double total = 0.0;
            #pragma unroll
            for (int w = 0; w < CELLS / 32; w++) total += dsum[w];
            out[0] = (float)(total / NBATCH);
            g_ticket = 0;   // reset for next graph replay
        }
    }
}

extern "C" void kernel_launch(void* const* d_in, const int* in_sizes, int n_in,
                              void* d_out, int out_size)
{
    const float* pred = (const float*)d_in[0];
    const float* tgt  = (const float*)d_in[1];
    float* out        = (float*)d_out;

    cudaFuncSetAttribute(yolo_loss_kernel,
                         cudaFuncAttributeMaxDynamicSharedMemorySize,
                         SMEM_BYTES);
    yolo_loss_kernel<<<NBLOCKS, CELLS, SMEM_BYTES>>>(pred, tgt, out);
}

// round 5
// speedup vs baseline: 1.1979x; 1.1979x over previous
#include <cuda_runtime.h>

// YOLO loss, sparsity-aware direct-load version.
// pred [8192, 49*30] f32, target [8192, 49*25] f32 -> scalar f32.
// Key fact: t0 in {0.0, 1.0}, P(obj)=0.05.
//   noobj cell: loss needs only t0, pc[0], pc[5]   (3 of 55 floats)
//   obj   cell: loss needs the full 55 floats      (5% of cells)
// Scalar predicated global loads -> ~38 MB DRAM sector traffic vs 91 MB
// for full staging. No shared-memory staging. 2 cells/thread for MLP.
// Fused deterministic reduction (ticket + last-block).

#define YS2       49
#define NT        256             // threads per block
#define CPT       2               // cells per thread
#define CPB       (NT * CPT)      // 512 cells per block
#define NBLOCKS   784             // 401408 / 512
#define NBATCH    8192.0

__device__ double       g_partials[NBLOCKS];
__device__ unsigned int g_ticket;      // zero-init; reset by last block

__global__ __launch_bounds__(NT) void yolo_loss_kernel(
    const float* __restrict__ pred, const float* __restrict__ tgt,
    float* __restrict__ out)
{
    const int tid  = threadIdx.x;
    const int base = blockIdx.x * CPB + tid;

    // ---- light loads: issued up front, fully independent (MLP=6) ----
    int   cell[CPT];
    float t0[CPT], p0[CPT], p5[CPT];
    #pragma unroll
    for (int k = 0; k < CPT; k++) {
        cell[k] = base + k * NT;                   // lanes consecutive
        t0[k] = __ldg(tgt  + (size_t)cell[k] * 25);
        p0[k] = __ldg(pred + (size_t)cell[k] * 30);
        p5[k] = __ldg(pred + (size_t)cell[k] * 30 + 5);
    }

    float acc = 0.0f;

    #pragma unroll
    for (int k = 0; k < CPT; k++) {
        if (t0[k] == 0.0f) {
            // noobj: LAMBDA_NOOBJ * (conf0^2 + conf1^2)
            acc += 0.5f * (p0[k] * p0[k] + p5[k] * p5[k]);
        } else if (t0[k] == 1.0f) {
            // obj cell: full loss, heavy loads predicated to ~5% of lanes
            const float* pc = pred + (size_t)cell[k] * 30;
            const float* tc = tgt  + (size_t)cell[k] * 25;

            const int g    = cell[k] % YS2;
            const float gy = (float)(g / 7);
            const float gx = (float)(g % 7);

            const float tx = __ldg(tc + 1), ty = __ldg(tc + 2);
            const float tw = __ldg(tc + 3), th = __ldg(tc + 4);
            const float tcx = (gx + tx) / 7.0f;
            const float tcy = (gy + ty) / 7.0f;
            const float tx1 = tcx - tw * 0.5f, ty1 = tcy - th * 0.5f;
            const float tx2 = tcx + tw * 0.5f, ty2 = tcy + th * 0.5f;
            const float area_t = (tx2 - tx1) * (ty2 - ty1);

            // both boxes' geometry
            float bx[2][4];
            #pragma unroll
            for (int bb = 0; bb < 2; bb++)
                #pragma unroll
                for (int j = 0; j < 4; j++)
                    bx[bb][j] = __ldg(pc + bb * 5 + 1 + j);

            float iou[2];
            #pragma unroll
            for (int bb = 0; bb < 2; bb++) {
                const float px = fabsf(bx[bb][0]);
                const float py = fabsf(bx[bb][1]);
                const float pw = fabsf(bx[bb][2]);
                const float ph = fabsf(bx[bb][3]);
                const float cx = (gx + px) / 7.0f;
                const float cy = (gy + py) / 7.0f;
                const float x1 = cx - pw * 0.5f, y1 = cy - ph * 0.5f;
                const float x2 = cx + pw * 0.5f, y2 = cy + ph * 0.5f;
                const float ltx = fmaxf(x1, tx1), lty = fmaxf(y1, ty1);
                const float rbx = fminf(x2, tx2), rby = fminf(y2, ty2);
                const float iw  = fmaxf(rbx - ltx, 0.0f);
                const float ih  = fmaxf(rby - lty, 0.0f);
                const float inter  = iw * ih;
                const float area_p = (x2 - x1) * (y2 - y1);
                iou[bb] = inter / (area_p + area_t - inter);
            }

            // argmax, tie -> box 0 (matches jnp.argmax first-occurrence)
            const int   best    = (iou[1] > iou[0]) ? 1 : 0;
            const float max_iou = best ? iou[1] : iou[0];
            const float rconf   = best ? p5[k] : p0[k];

            const float dx = bx[best][0] - tx;
            const float dy = bx[best][1] - ty;
            const float xy_loss = dx * dx + dy * dy;

            const float swd = sqrtf(fabsf(bx[best][2])) - sqrtf(fabsf(tw));
            const float shd = sqrtf(fabsf(bx[best][3])) - sqrtf(fabsf(th));
            const float wh_loss = swd * swd + shd * shd;

            const float doc = rconf - max_iou;
            const float obj_conf = doc * doc;

            float cls = 0.0f;
            #pragma unroll
            for (int j = 0; j < 20; j++) {
                const float d = __ldg(pc + 10 + j) - __ldg(tc + 5 + j);
                cls += d * d;
            }

            acc += 5.0f * (xy_loss + wh_loss) + obj_conf + cls;
        }
    }

    // ---- deterministic block reduction ----
    #pragma unroll
    for (int o = 16; o > 0; o >>= 1)
        acc += __shfl_down_sync(0xffffffffu, acc, o);

    __shared__ float wsum[NT / 32];
    __shared__ int   s_last;
    const int lane = tid & 31;
    const int wrp  = tid >> 5;
    if (lane == 0) wsum[wrp] = acc;
    __syncthreads();

    if (tid == 0) {
        double s = 0.0;
        #pragma unroll
        for (int w = 0; w < NT / 32; w++) s += (double)wsum[w];
        g_partials[blockIdx.x] = s;
        __threadfence();
        unsigned int ticket = atomicAdd(&g_ticket, 1u);
        s_last = (ticket == NBLOCKS - 1u) ? 1 : 0;
    }
    __syncthreads();

    // ---- last block: final reduction over all partials ----
    if (s_last) {
        __threadfence();
        __shared__ double dsum[NT / 32];

        double s = 0.0;
        for (int i = tid; i < NBLOCKS; i += NT)
            s += g_partials[i];

        #pragma unroll
        for (int o = 16; o > 0; o >>= 1)
            s += __shfl_down_sync(0xffffffffu, s, o);

        if (lane == 0) dsum[wrp] = s;
        __syncthreads();

        if (tid == 0) {
            double total = 0.0;
            #pragma unroll
            for (int w = 0; w < NT / 32; w++) total += dsum[w];
            out[0] = (float)(total / NBATCH);
            g_ticket = 0;   // reset for next graph replay
        }
    }
}

extern "C" void kernel_launch(void* const* d_in, const int* in_sizes, int n_in,
                              void* d_out, int out_size)
{
    const float* pred = (const float*)d_in[0];
    const float* tgt  = (const float*)d_in[1];
    float* out        = (float*)d_out;

    yolo_loss_kernel<<<NBLOCKS, NT>>>(pred, tgt, out);
}